// round 2
// baseline (speedup 1.0000x reference)
#include <cuda_runtime.h>

#define NNODES_C 10000

__device__ float g_nodeftr[NNODES_C * 20];

static __device__ __forceinline__ float4 f4fma(float s, float4 w, float4 a) {
    a.x = fmaf(s, w.x, a.x);
    a.y = fmaf(s, w.y, a.y);
    a.z = fmaf(s, w.z, a.z);
    a.w = fmaf(s, w.w, a.w);
    return a;
}

__global__ void zero_nf_kernel(int n) {
    int i = blockIdx.x * blockDim.x + threadIdx.x;
    if (i < n) g_nodeftr[i] = 0.0f;
}

__global__ __launch_bounds__(256) void edge_kernel(
    const float* __restrict__ hn, const float* __restrict__ he,
    const int* __restrict__ esrc, const int* __restrict__ edst,
    const float* __restrict__ evec, const float* __restrict__ emb,
    const float* __restrict__ enorm,
    const float* __restrict__ fcW1, const float* __restrict__ fcW2,
    const float* __restrict__ fc2W1, const float* __restrict__ fc2W2,
    float* __restrict__ out_he, int E)
{
    const float SQ3f    = 1.7320508075688772f;
    const float INVSQ3f = 0.57735026918962576f;
    const float RS10    = 0.31622776601683794f;   // 1/sqrt(10)
    const float CS1     = 0.14433756729740645f;   // 1/sqrt(48)
    const float CV1     = 0.20412414523193150f;   // 1/sqrt(24)
    const float CS2     = 0.25f;                  // 1/sqrt(16)
    const float CV2     = 0.35355339059327379f;   // 1/sqrt(8)

    __shared__ __align__(16) float sW1 [160];
    __shared__ __align__(16) float sW1b[160];
    __shared__ __align__(16) float sW2 [9216];
    __shared__ __align__(16) float sW2b[2304];

    for (int t = threadIdx.x; t < 160;  t += 256) { sW1[t] = fcW1[t]*RS10; sW1b[t] = fc2W1[t]*RS10; }
    for (int t = threadIdx.x; t < 9216; t += 256) sW2[t]  = fcW2[t]*0.25f;
    for (int t = threadIdx.x; t < 2304; t += 256) sW2b[t] = fc2W2[t]*0.25f;
    __syncthreads();

    int e = blockIdx.x*256 + threadIdx.x;
    if (e >= E) return;

    // ---- per-edge inputs ----
    float embr[10];
#pragma unroll
    for (int j = 0; j < 10; j++) embr[j] = emb[e*10 + j];

    float s[24], v[12][3];
    {
        const float* p = he + (size_t)e*20;
#pragma unroll
        for (int j = 0; j < 8; j++) s[j] = p[j];
#pragma unroll
        for (int i = 0; i < 4; i++)
#pragma unroll
            for (int c = 0; c < 3; c++) v[i][c] = p[8 + i*3 + c];
    }
    int srcI = esrc[e], dstI = edst[e];
    {
        const float* p = hn + (size_t)srcI*20;
#pragma unroll
        for (int j = 0; j < 8; j++) s[8+j] = p[j];
#pragma unroll
        for (int i = 0; i < 4; i++)
#pragma unroll
            for (int c = 0; c < 3; c++) v[4+i][c] = p[8 + i*3 + c];
    }
    {
        const float* p = hn + (size_t)dstI*20;
#pragma unroll
        for (int j = 0; j < 8; j++) s[16+j] = p[j];
#pragma unroll
        for (int i = 0; i < 4; i++)
#pragma unroll
            for (int c = 0; c < 3; c++) v[8+i][c] = p[8 + i*3 + c];
    }

    float sh1[3];
    {
        float ex = evec[e*3+0], ey = evec[e*3+1], ez = evec[e*3+2];
        float nn = sqrtf(ex*ex + ey*ey + ez*ez) + 1e-12f;
        float f = SQ3f / nn;
        sh1[0] = ex*f; sh1[1] = ey*f; sh1[2] = ez*f;
    }

    // ---- h1 = relu(emb @ fcW1/sqrt(10)) ----
    float h1[16];
    {
        const float4* W = (const float4*)sW1;
        float4 acc[4];
#pragma unroll
        for (int g = 0; g < 4; g++) acc[g] = make_float4(0.f,0.f,0.f,0.f);
#pragma unroll
        for (int j = 0; j < 10; j++) {
            float ej = embr[j];
#pragma unroll
            for (int g = 0; g < 4; g++) acc[g] = f4fma(ej, W[j*4+g], acc[g]);
        }
#pragma unroll
        for (int g = 0; g < 4; g++) {
            h1[g*4+0] = fmaxf(acc[g].x, 0.f);
            h1[g*4+1] = fmaxf(acc[g].y, 0.f);
            h1[g*4+2] = fmaxf(acc[g].z, 0.f);
            h1[g*4+3] = fmaxf(acc[g].w, 0.f);
        }
    }

    // ---- TP1: w = h1 @ (fcW2/4); contract on the fly ----
    const float4* W2 = (const float4*)sW2;   // 144 float4 per k-row
    float a0s[12], a0v[12], asv[4], a1[4][3];
#pragma unroll
    for (int o = 0; o < 12; o++) { a0s[o] = 0.f; a0v[o] = 0.f; }
#pragma unroll
    for (int o = 0; o < 4; o++) { asv[o] = 0.f; a1[o][0]=0.f; a1[o][1]=0.f; a1[o][2]=0.f; }

    // ss: cols [0,288), col = i*12+o
#pragma unroll
    for (int i = 0; i < 24; i++) {
        float si = s[i];
#pragma unroll
        for (int g = 0; g < 3; g++) {
            float4 a = make_float4(0.f,0.f,0.f,0.f);
#pragma unroll
            for (int k = 0; k < 16; k++) a = f4fma(h1[k], W2[k*144 + i*3 + g], a);
            a0s[g*4+0] = fmaf(si, a.x, a0s[g*4+0]);
            a0s[g*4+1] = fmaf(si, a.y, a0s[g*4+1]);
            a0s[g*4+2] = fmaf(si, a.z, a0s[g*4+2]);
            a0s[g*4+3] = fmaf(si, a.w, a0s[g*4+3]);
        }
    }
    // vs: cols [288,432), col = 288 + i*12 + o
#pragma unroll
    for (int i = 0; i < 12; i++) {
        float di = (v[i][0]*sh1[0] + v[i][1]*sh1[1] + v[i][2]*sh1[2]) * INVSQ3f;
#pragma unroll
        for (int g = 0; g < 3; g++) {
            float4 a = make_float4(0.f,0.f,0.f,0.f);
#pragma unroll
            for (int k = 0; k < 16; k++) a = f4fma(h1[k], W2[k*144 + 72 + i*3 + g], a);
            a0v[g*4+0] = fmaf(di, a.x, a0v[g*4+0]);
            a0v[g*4+1] = fmaf(di, a.y, a0v[g*4+1]);
            a0v[g*4+2] = fmaf(di, a.z, a0v[g*4+2]);
            a0v[g*4+3] = fmaf(di, a.w, a0v[g*4+3]);
        }
    }
    // sv: cols [432,528), col = 432 + i*4 + o
#pragma unroll
    for (int i = 0; i < 24; i++) {
        float4 a = make_float4(0.f,0.f,0.f,0.f);
#pragma unroll
        for (int k = 0; k < 16; k++) a = f4fma(h1[k], W2[k*144 + 108 + i], a);
        float si = s[i];
        asv[0] = fmaf(si, a.x, asv[0]);
        asv[1] = fmaf(si, a.y, asv[1]);
        asv[2] = fmaf(si, a.z, asv[2]);
        asv[3] = fmaf(si, a.w, asv[3]);
    }
    // vv: cols [528,576), col = 528 + i*4 + o
#pragma unroll
    for (int i = 0; i < 12; i++) {
        float4 a = make_float4(0.f,0.f,0.f,0.f);
#pragma unroll
        for (int k = 0; k < 16; k++) a = f4fma(h1[k], W2[k*144 + 132 + i], a);
#pragma unroll
        for (int c = 0; c < 3; c++) {
            float vc = v[i][c];
            a1[0][c] = fmaf(vc, a.x, a1[0][c]);
            a1[1][c] = fmaf(vc, a.y, a1[1][c]);
            a1[2][c] = fmaf(vc, a.z, a1[2][c]);
            a1[3][c] = fmaf(vc, a.w, a1[3][c]);
        }
    }

    // gating
    float ts[8], gate[4], tv[4][3];
#pragma unroll
    for (int o = 0; o < 8; o++) ts[o] = fmaxf(CS1*a0s[o] + CV1*a0v[o], 0.f);
#pragma unroll
    for (int o = 0; o < 4; o++) gate[o] = fmaxf(CS1*a0s[8+o] + CV1*a0v[8+o], 0.f);
#pragma unroll
    for (int o = 0; o < 4; o++)
#pragma unroll
        for (int c = 0; c < 3; c++)
            tv[o][c] = (CS1*asv[o]*sh1[c] + CV1*a1[o][c]) * gate[o];

    // ---- h2 = relu(emb @ fc2W1/sqrt(10)) ----
    float h2[16];
    {
        const float4* W = (const float4*)sW1b;
        float4 acc[4];
#pragma unroll
        for (int g = 0; g < 4; g++) acc[g] = make_float4(0.f,0.f,0.f,0.f);
#pragma unroll
        for (int j = 0; j < 10; j++) {
            float ej = embr[j];
#pragma unroll
            for (int g = 0; g < 4; g++) acc[g] = f4fma(ej, W[j*4+g], acc[g]);
        }
#pragma unroll
        for (int g = 0; g < 4; g++) {
            h2[g*4+0] = fmaxf(acc[g].x, 0.f);
            h2[g*4+1] = fmaxf(acc[g].y, 0.f);
            h2[g*4+2] = fmaxf(acc[g].z, 0.f);
            h2[g*4+3] = fmaxf(acc[g].w, 0.f);
        }
    }

    // ---- TP2 ----
    const float4* W2b = (const float4*)sW2b;  // 36 float4 per k-row
    float b0s[8], b0v[8], bsv[4], b1[4][3];
#pragma unroll
    for (int o = 0; o < 8; o++) { b0s[o] = 0.f; b0v[o] = 0.f; }
#pragma unroll
    for (int o = 0; o < 4; o++) { bsv[o] = 0.f; b1[o][0]=0.f; b1[o][1]=0.f; b1[o][2]=0.f; }

    // ss: col = i*8+o, i<8
#pragma unroll
    for (int i = 0; i < 8; i++) {
        float si = ts[i];
#pragma unroll
        for (int g = 0; g < 2; g++) {
            float4 a = make_float4(0.f,0.f,0.f,0.f);
#pragma unroll
            for (int k = 0; k < 16; k++) a = f4fma(h2[k], W2b[k*36 + i*2 + g], a);
            b0s[g*4+0] = fmaf(si, a.x, b0s[g*4+0]);
            b0s[g*4+1] = fmaf(si, a.y, b0s[g*4+1]);
            b0s[g*4+2] = fmaf(si, a.z, b0s[g*4+2]);
            b0s[g*4+3] = fmaf(si, a.w, b0s[g*4+3]);
        }
    }
    // vs: col = 64 + i*8 + o, i<4
#pragma unroll
    for (int i = 0; i < 4; i++) {
        float di = (tv[i][0]*sh1[0] + tv[i][1]*sh1[1] + tv[i][2]*sh1[2]) * INVSQ3f;
#pragma unroll
        for (int g = 0; g < 2; g++) {
            float4 a = make_float4(0.f,0.f,0.f,0.f);
#pragma unroll
            for (int k = 0; k < 16; k++) a = f4fma(h2[k], W2b[k*36 + 16 + i*2 + g], a);
            b0v[g*4+0] = fmaf(di, a.x, b0v[g*4+0]);
            b0v[g*4+1] = fmaf(di, a.y, b0v[g*4+1]);
            b0v[g*4+2] = fmaf(di, a.z, b0v[g*4+2]);
            b0v[g*4+3] = fmaf(di, a.w, b0v[g*4+3]);
        }
    }
    // sv: col = 96 + i*4 + o, i<8
#pragma unroll
    for (int i = 0; i < 8; i++) {
        float4 a = make_float4(0.f,0.f,0.f,0.f);
#pragma unroll
        for (int k = 0; k < 16; k++) a = f4fma(h2[k], W2b[k*36 + 24 + i], a);
        float si = ts[i];
        bsv[0] = fmaf(si, a.x, bsv[0]);
        bsv[1] = fmaf(si, a.y, bsv[1]);
        bsv[2] = fmaf(si, a.z, bsv[2]);
        bsv[3] = fmaf(si, a.w, bsv[3]);
    }
    // vv: col = 128 + i*4 + o, i<4
#pragma unroll
    for (int i = 0; i < 4; i++) {
        float4 a = make_float4(0.f,0.f,0.f,0.f);
#pragma unroll
        for (int k = 0; k < 16; k++) a = f4fma(h2[k], W2b[k*36 + 32 + i], a);
#pragma unroll
        for (int c = 0; c < 3; c++) {
            float vc = tv[i][c];
            b1[0][c] = fmaf(vc, a.x, b1[0][c]);
            b1[1][c] = fmaf(vc, a.y, b1[1][c]);
            b1[2][c] = fmaf(vc, a.z, b1[2][c]);
            b1[3][c] = fmaf(vc, a.w, b1[3][c]);
        }
    }

    // ---- he_new + scatter ----
    float hnew[20];
#pragma unroll
    for (int j = 0; j < 8; j++) hnew[j] = s[j] + (CS2*b0s[j] + CV2*b0v[j]);
#pragma unroll
    for (int o = 0; o < 4; o++)
#pragma unroll
        for (int c = 0; c < 3; c++)
            hnew[8 + o*3 + c] = v[o][c] + (CS2*bsv[o]*sh1[c] + CV2*b1[o][c]);

    float* op = out_he + (size_t)e*20;
    float nw = enorm[e];
    float* nf = &g_nodeftr[(size_t)dstI*20];
#pragma unroll
    for (int t = 0; t < 20; t++) {
        op[t] = hnew[t];
        atomicAdd(&nf[t], hnew[t]*nw);
    }
}

__global__ __launch_bounds__(128) void node_kernel(
    const float* __restrict__ hn,
    const float* __restrict__ WgS, const float* __restrict__ WgV,
    const float* __restrict__ WoS, const float* __restrict__ WoV,
    float* __restrict__ out_hn, int N)
{
    const float RS8 = 0.35355339059327379f;  // 1/sqrt(8)
    int n = blockIdx.x*128 + threadIdx.x;
    if (n >= N) return;

    float cs[16], cv[8][3];
    const float* ph = hn + (size_t)n*20;
    const float* pf = g_nodeftr + (size_t)n*20;
#pragma unroll
    for (int j = 0; j < 8; j++) { cs[j] = ph[j]; cs[8+j] = pf[j]; }
#pragma unroll
    for (int i = 0; i < 4; i++)
#pragma unroll
        for (int c = 0; c < 3; c++) { cv[i][c] = ph[8+i*3+c]; cv[4+i][c] = pf[8+i*3+c]; }

    float gl[12];
#pragma unroll
    for (int o = 0; o < 12; o++) {
        float a = 0.f;
#pragma unroll
        for (int i = 0; i < 16; i++) a = fmaf(cs[i], __ldg(&WgS[i*12+o]), a);
        gl[o] = a * 0.25f;
    }
    float vl[4][3];
#pragma unroll
    for (int o = 0; o < 4; o++)
#pragma unroll
        for (int c = 0; c < 3; c++) {
            float a = 0.f;
#pragma unroll
            for (int i = 0; i < 8; i++) a = fmaf(cv[i][c], __ldg(&WgV[i*4+o]), a);
            vl[o][c] = a * RS8;
        }

    float ls[8], lg[4];
#pragma unroll
    for (int j = 0; j < 8; j++) ls[j] = fmaxf(gl[j], 0.f);
#pragma unroll
    for (int o = 0; o < 4; o++) lg[o] = fmaxf(gl[8+o], 0.f);

    float lv[4][3];
#pragma unroll
    for (int o = 0; o < 4; o++)
#pragma unroll
        for (int c = 0; c < 3; c++) lv[o][c] = vl[o][c] * lg[o];

    float os_[8];
#pragma unroll
    for (int o = 0; o < 8; o++) {
        float a = 0.f;
#pragma unroll
        for (int i = 0; i < 8; i++) a = fmaf(ls[i], __ldg(&WoS[i*8+o]), a);
        os_[o] = a * RS8;
    }
    float ov[4][3];
#pragma unroll
    for (int o = 0; o < 4; o++)
#pragma unroll
        for (int c = 0; c < 3; c++) {
            float a = 0.f;
#pragma unroll
            for (int i = 0; i < 4; i++) a = fmaf(lv[i][c], __ldg(&WoV[i*4+o]), a);
            ov[o][c] = a * 0.5f;
        }

    float* po = out_hn + (size_t)n*20;
#pragma unroll
    for (int j = 0; j < 8; j++) po[j] = ph[j] + os_[j];
#pragma unroll
    for (int o = 0; o < 4; o++)
#pragma unroll
        for (int c = 0; c < 3; c++) po[8+o*3+c] = ph[8+o*3+c] + ov[o][c];
}

extern "C" void kernel_launch(void* const* d_in, const int* in_sizes, int n_in,
                              void* d_out, int out_size) {
    const float* hn    = (const float*)d_in[0];
    const float* he    = (const float*)d_in[1];
    const int*   esrc  = (const int*)d_in[2];
    const int*   edst  = (const int*)d_in[3];
    const float* evec  = (const float*)d_in[4];
    const float* emb   = (const float*)d_in[5];
    const float* enorm = (const float*)d_in[6];
    // d_in[7] = num_nodes (scalar, unused; N from sizes)
    const float* fcW1  = (const float*)d_in[8];
    const float* fcW2  = (const float*)d_in[9];
    const float* fc2W1 = (const float*)d_in[10];
    const float* fc2W2 = (const float*)d_in[11];
    const float* WgS   = (const float*)d_in[12];
    const float* WgV   = (const float*)d_in[13];
    const float* WoS   = (const float*)d_in[14];
    const float* WoV   = (const float*)d_in[15];

    int N = in_sizes[0] / 20;
    int E = in_sizes[1] / 20;

    float* out    = (float*)d_out;
    float* out_hn = out;                      // (N,20) first
    float* out_he = out + (size_t)N * 20;     // (E,20) second

    int nf = N * 20;
    zero_nf_kernel<<<(nf + 255)/256, 256>>>(nf);
    edge_kernel<<<(E + 255)/256, 256>>>(hn, he, esrc, edst, evec, emb, enorm,
                                        fcW1, fcW2, fc2W1, fc2W2, out_he, E);
    node_kernel<<<(N + 127)/128, 128>>>(hn, WgS, WgV, WoS, WoV, out_hn, N);
}

// round 3
// speedup vs baseline: 1.9260x; 1.9260x over previous
#include <cuda_runtime.h>

#define NNODES_C 10000
typedef unsigned long long u64;

__device__ float g_nodeftr[NNODES_C * 20];

static __device__ __forceinline__ u64 pack2(float x) {
    u64 r;
    asm("mov.b64 %0, {%1, %1};" : "=l"(r) : "r"(__float_as_uint(x)));
    return r;
}
static __device__ __forceinline__ float2 unpack2(u64 v) {
    float lo, hi;
    asm("mov.b64 {%0, %1}, %2;" : "=f"(lo), "=f"(hi) : "l"(v));
    return make_float2(lo, hi);
}
static __device__ __forceinline__ u64 fma2(u64 a, u64 b, u64 c) {
    u64 d;
    asm("fma.rn.f32x2 %0, %1, %2, %3;" : "=l"(d) : "l"(a), "l"(b), "l"(c));
    return d;
}

__global__ void zero_nf_kernel(int n4) {
    int i = blockIdx.x * blockDim.x + threadIdx.x;
    if (i < n4) ((float4*)g_nodeftr)[i] = make_float4(0.f, 0.f, 0.f, 0.f);
}

__global__ __launch_bounds__(128) void edge_kernel(
    const float* __restrict__ hn, const float* __restrict__ he,
    const int* __restrict__ esrc, const int* __restrict__ edst,
    const float* __restrict__ evec, const float* __restrict__ emb,
    const float* __restrict__ enorm,
    const float* __restrict__ fcW1, const float* __restrict__ fcW2,
    const float* __restrict__ fc2W1, const float* __restrict__ fc2W2,
    float* __restrict__ out_he, int E)
{
    const float SQ3f    = 1.7320508075688772f;
    const float INVSQ3f = 0.57735026918962576f;
    const float RS10    = 0.31622776601683794f;   // 1/sqrt(10)
    const float CS1     = 0.14433756729740645f;   // 1/sqrt(48)
    const float CV1     = 0.20412414523193150f;   // 1/sqrt(24)
    const float CS2     = 0.25f;                  // 1/sqrt(16)
    const float CV2     = 0.35355339059327379f;   // 1/sqrt(8)

    __shared__ __align__(16) float sW1 [160];
    __shared__ __align__(16) float sW1b[160];
    __shared__ __align__(16) float sW2 [9216];
    __shared__ __align__(16) float sW2b[2304];

    // vectorized staging with scales folded in
    {
        const float4* g1 = (const float4*)fcW1;
        const float4* g1b = (const float4*)fc2W1;
        float4* d1 = (float4*)sW1;  float4* d1b = (float4*)sW1b;
        for (int t = threadIdx.x; t < 40; t += 128) {
            float4 a = g1[t];  d1[t]  = make_float4(a.x*RS10, a.y*RS10, a.z*RS10, a.w*RS10);
            float4 b = g1b[t]; d1b[t] = make_float4(b.x*RS10, b.y*RS10, b.z*RS10, b.w*RS10);
        }
        const float4* g2 = (const float4*)fcW2;
        float4* d2 = (float4*)sW2;
        for (int t = threadIdx.x; t < 2304; t += 128) {
            float4 a = g2[t]; d2[t] = make_float4(a.x*0.25f, a.y*0.25f, a.z*0.25f, a.w*0.25f);
        }
        const float4* g2b = (const float4*)fc2W2;
        float4* d2b = (float4*)sW2b;
        for (int t = threadIdx.x; t < 576; t += 128) {
            float4 a = g2b[t]; d2b[t] = make_float4(a.x*0.25f, a.y*0.25f, a.z*0.25f, a.w*0.25f);
        }
    }
    __syncthreads();

    int e = blockIdx.x*128 + threadIdx.x;
    if (e >= E) return;

    // ---- gather per-edge rows (float4) ----
    int srcI = esrc[e], dstI = edst[e];
    float4 rowE[5], rowS[5], rowD[5];
    {
        const float4* p = (const float4*)(he + (size_t)e*20);
#pragma unroll
        for (int i = 0; i < 5; i++) rowE[i] = p[i];
        const float4* ps = (const float4*)(hn + (size_t)srcI*20);
#pragma unroll
        for (int i = 0; i < 5; i++) rowS[i] = ps[i];
        const float4* pd = (const float4*)(hn + (size_t)dstI*20);
#pragma unroll
        for (int i = 0; i < 5; i++) rowD[i] = pd[i];
    }
    float s[24], vf[36];   // vf[i*3+c]
    {
        const float* re = (const float*)rowE;
        const float* rs = (const float*)rowS;
        const float* rd = (const float*)rowD;
#pragma unroll
        for (int j = 0; j < 8; j++) { s[j] = re[j]; s[8+j] = rs[j]; s[16+j] = rd[j]; }
#pragma unroll
        for (int j = 0; j < 12; j++) { vf[j] = re[8+j]; vf[12+j] = rs[8+j]; vf[24+j] = rd[8+j]; }
    }

    float sh1[3];
    {
        float ex = evec[e*3+0], ey = evec[e*3+1], ez = evec[e*3+2];
        float nn = sqrtf(ex*ex + ey*ey + ez*ez) + 1e-12f;
        float f = SQ3f / nn;
        sh1[0] = ex*f; sh1[1] = ey*f; sh1[2] = ez*f;
    }

    // ---- h1 = relu(emb @ fcW1/sqrt(10)), packed ----
    u64 h1p[16];
    {
        float embr[10];
        const float2* pe2 = (const float2*)(emb + (size_t)e*10);
#pragma unroll
        for (int j = 0; j < 5; j++) { float2 t = pe2[j]; embr[2*j] = t.x; embr[2*j+1] = t.y; }
        const ulonglong2* W = (const ulonglong2*)sW1;
        u64 acc[8];
#pragma unroll
        for (int p = 0; p < 8; p++) acc[p] = 0ull;
#pragma unroll
        for (int j = 0; j < 10; j++) {
            u64 ej = pack2(embr[j]);
#pragma unroll
            for (int g = 0; g < 4; g++) {
                ulonglong2 w = W[j*4+g];
                acc[2*g]   = fma2(ej, w.x, acc[2*g]);
                acc[2*g+1] = fma2(ej, w.y, acc[2*g+1]);
            }
        }
#pragma unroll
        for (int p = 0; p < 8; p++) {
            float2 f = unpack2(acc[p]);
            h1p[2*p]   = pack2(fmaxf(f.x, 0.f));
            h1p[2*p+1] = pack2(fmaxf(f.y, 0.f));
        }
    }

    // ---- TP1, packed f32x2 ----
    const ulonglong2* W2 = (const ulonglong2*)sW2;   // 144 chunks per k-row

    float dots[12];
#pragma unroll
    for (int i = 0; i < 12; i++)
        dots[i] = (vf[i*3+0]*sh1[0] + vf[i*3+1]*sh1[1] + vf[i*3+2]*sh1[2]) * INVSQ3f;

    u64 a1p[2][3];
#pragma unroll
    for (int c = 0; c < 3; c++) { a1p[0][c] = 0ull; a1p[1][c] = 0ull; }
    // vv: chunk 132 + i
#pragma unroll
    for (int i = 0; i < 12; i++) {
        u64 aA = 0ull, aB = 0ull;
#pragma unroll
        for (int k = 0; k < 16; k++) {
            ulonglong2 w = W2[k*144 + 132 + i];
            aA = fma2(h1p[k], w.x, aA);
            aB = fma2(h1p[k], w.y, aB);
        }
#pragma unroll
        for (int c = 0; c < 3; c++) {
            u64 vc2 = pack2(vf[i*3+c]);
            a1p[0][c] = fma2(vc2, aA, a1p[0][c]);
            a1p[1][c] = fma2(vc2, aB, a1p[1][c]);
        }
    }
    // vs: chunk 72 + i*3 + g
    u64 a0vp[6];
#pragma unroll
    for (int p = 0; p < 6; p++) a0vp[p] = 0ull;
#pragma unroll
    for (int i = 0; i < 12; i++) {
        u64 di2 = pack2(dots[i]);
#pragma unroll
        for (int g = 0; g < 3; g++) {
            u64 aA = 0ull, aB = 0ull;
#pragma unroll
            for (int k = 0; k < 16; k++) {
                ulonglong2 w = W2[k*144 + 72 + i*3 + g];
                aA = fma2(h1p[k], w.x, aA);
                aB = fma2(h1p[k], w.y, aB);
            }
            a0vp[2*g]   = fma2(di2, aA, a0vp[2*g]);
            a0vp[2*g+1] = fma2(di2, aB, a0vp[2*g+1]);
        }
    }
    // ss: chunk i*3 + g
    u64 a0sp[6];
#pragma unroll
    for (int p = 0; p < 6; p++) a0sp[p] = 0ull;
#pragma unroll
    for (int i = 0; i < 24; i++) {
        u64 si2 = pack2(s[i]);
#pragma unroll
        for (int g = 0; g < 3; g++) {
            u64 aA = 0ull, aB = 0ull;
#pragma unroll
            for (int k = 0; k < 16; k++) {
                ulonglong2 w = W2[k*144 + i*3 + g];
                aA = fma2(h1p[k], w.x, aA);
                aB = fma2(h1p[k], w.y, aB);
            }
            a0sp[2*g]   = fma2(si2, aA, a0sp[2*g]);
            a0sp[2*g+1] = fma2(si2, aB, a0sp[2*g+1]);
        }
    }
    // sv: chunk 108 + i
    u64 asvp[2];
    asvp[0] = 0ull; asvp[1] = 0ull;
#pragma unroll
    for (int i = 0; i < 24; i++) {
        u64 aA = 0ull, aB = 0ull;
#pragma unroll
        for (int k = 0; k < 16; k++) {
            ulonglong2 w = W2[k*144 + 108 + i];
            aA = fma2(h1p[k], w.x, aA);
            aB = fma2(h1p[k], w.y, aB);
        }
        u64 si2 = pack2(s[i]);
        asvp[0] = fma2(si2, aA, asvp[0]);
        asvp[1] = fma2(si2, aB, asvp[1]);
    }

    // ---- gating ----
    float ts[8], tv[12], dt[4];
    {
        float a0s[12], a0v[12], asv[4], a1[4][3];
#pragma unroll
        for (int p = 0; p < 6; p++) {
            float2 fs = unpack2(a0sp[p]); a0s[2*p] = fs.x; a0s[2*p+1] = fs.y;
            float2 fv = unpack2(a0vp[p]); a0v[2*p] = fv.x; a0v[2*p+1] = fv.y;
        }
        {
            float2 f0 = unpack2(asvp[0]); float2 f1 = unpack2(asvp[1]);
            asv[0] = f0.x; asv[1] = f0.y; asv[2] = f1.x; asv[3] = f1.y;
        }
#pragma unroll
        for (int c = 0; c < 3; c++) {
            float2 f0 = unpack2(a1p[0][c]); float2 f1 = unpack2(a1p[1][c]);
            a1[0][c] = f0.x; a1[1][c] = f0.y; a1[2][c] = f1.x; a1[3][c] = f1.y;
        }
#pragma unroll
        for (int o = 0; o < 8; o++) ts[o] = fmaxf(CS1*a0s[o] + CV1*a0v[o], 0.f);
#pragma unroll
        for (int o = 0; o < 4; o++) {
            float gate = fmaxf(CS1*a0s[8+o] + CV1*a0v[8+o], 0.f);
#pragma unroll
            for (int c = 0; c < 3; c++)
                tv[o*3+c] = (CS1*asv[o]*sh1[c] + CV1*a1[o][c]) * gate;
        }
#pragma unroll
        for (int i = 0; i < 4; i++)
            dt[i] = (tv[i*3+0]*sh1[0] + tv[i*3+1]*sh1[1] + tv[i*3+2]*sh1[2]) * INVSQ3f;
    }

    // ---- h2 = relu(emb @ fc2W1/sqrt(10)), packed (reload emb) ----
    u64 h2p[16];
    {
        float embr[10];
        const float2* pe2 = (const float2*)(emb + (size_t)e*10);
#pragma unroll
        for (int j = 0; j < 5; j++) { float2 t = pe2[j]; embr[2*j] = t.x; embr[2*j+1] = t.y; }
        const ulonglong2* W = (const ulonglong2*)sW1b;
        u64 acc[8];
#pragma unroll
        for (int p = 0; p < 8; p++) acc[p] = 0ull;
#pragma unroll
        for (int j = 0; j < 10; j++) {
            u64 ej = pack2(embr[j]);
#pragma unroll
            for (int g = 0; g < 4; g++) {
                ulonglong2 w = W[j*4+g];
                acc[2*g]   = fma2(ej, w.x, acc[2*g]);
                acc[2*g+1] = fma2(ej, w.y, acc[2*g+1]);
            }
        }
#pragma unroll
        for (int p = 0; p < 8; p++) {
            float2 f = unpack2(acc[p]);
            h2p[2*p]   = pack2(fmaxf(f.x, 0.f));
            h2p[2*p+1] = pack2(fmaxf(f.y, 0.f));
        }
    }

    // ---- TP2, packed ----
    const ulonglong2* W2b = (const ulonglong2*)sW2b;  // 36 chunks per k-row
    u64 b0sp[4], b0vp[4], bsvp[2], b1p[2][3];
#pragma unroll
    for (int p = 0; p < 4; p++) { b0sp[p] = 0ull; b0vp[p] = 0ull; }
    bsvp[0] = 0ull; bsvp[1] = 0ull;
#pragma unroll
    for (int c = 0; c < 3; c++) { b1p[0][c] = 0ull; b1p[1][c] = 0ull; }

    // ss: chunk i*2 + g
#pragma unroll
    for (int i = 0; i < 8; i++) {
        u64 si2 = pack2(ts[i]);
#pragma unroll
        for (int g = 0; g < 2; g++) {
            u64 aA = 0ull, aB = 0ull;
#pragma unroll
            for (int k = 0; k < 16; k++) {
                ulonglong2 w = W2b[k*36 + i*2 + g];
                aA = fma2(h2p[k], w.x, aA);
                aB = fma2(h2p[k], w.y, aB);
            }
            b0sp[2*g]   = fma2(si2, aA, b0sp[2*g]);
            b0sp[2*g+1] = fma2(si2, aB, b0sp[2*g+1]);
        }
    }
    // vs: chunk 16 + i*2 + g
#pragma unroll
    for (int i = 0; i < 4; i++) {
        u64 di2 = pack2(dt[i]);
#pragma unroll
        for (int g = 0; g < 2; g++) {
            u64 aA = 0ull, aB = 0ull;
#pragma unroll
            for (int k = 0; k < 16; k++) {
                ulonglong2 w = W2b[k*36 + 16 + i*2 + g];
                aA = fma2(h2p[k], w.x, aA);
                aB = fma2(h2p[k], w.y, aB);
            }
            b0vp[2*g]   = fma2(di2, aA, b0vp[2*g]);
            b0vp[2*g+1] = fma2(di2, aB, b0vp[2*g+1]);
        }
    }
    // sv: chunk 24 + i
#pragma unroll
    for (int i = 0; i < 8; i++) {
        u64 aA = 0ull, aB = 0ull;
#pragma unroll
        for (int k = 0; k < 16; k++) {
            ulonglong2 w = W2b[k*36 + 24 + i];
            aA = fma2(h2p[k], w.x, aA);
            aB = fma2(h2p[k], w.y, aB);
        }
        u64 si2 = pack2(ts[i]);
        bsvp[0] = fma2(si2, aA, bsvp[0]);
        bsvp[1] = fma2(si2, aB, bsvp[1]);
    }
    // vv: chunk 32 + i
#pragma unroll
    for (int i = 0; i < 4; i++) {
        u64 aA = 0ull, aB = 0ull;
#pragma unroll
        for (int k = 0; k < 16; k++) {
            ulonglong2 w = W2b[k*36 + 32 + i];
            aA = fma2(h2p[k], w.x, aA);
            aB = fma2(h2p[k], w.y, aB);
        }
#pragma unroll
        for (int c = 0; c < 3; c++) {
            u64 vc2 = pack2(tv[i*3+c]);
            b1p[0][c] = fma2(vc2, aA, b1p[0][c]);
            b1p[1][c] = fma2(vc2, aB, b1p[1][c]);
        }
    }

    // ---- epilogue: he_new + scatter ----
    float b0s[8], b0v[8], bsv[4], b1[4][3];
#pragma unroll
    for (int p = 0; p < 4; p++) {
        float2 fs = unpack2(b0sp[p]); b0s[2*p] = fs.x; b0s[2*p+1] = fs.y;
        float2 fv = unpack2(b0vp[p]); b0v[2*p] = fv.x; b0v[2*p+1] = fv.y;
    }
    {
        float2 f0 = unpack2(bsvp[0]); float2 f1 = unpack2(bsvp[1]);
        bsv[0] = f0.x; bsv[1] = f0.y; bsv[2] = f1.x; bsv[3] = f1.y;
    }
#pragma unroll
    for (int c = 0; c < 3; c++) {
        float2 f0 = unpack2(b1p[0][c]); float2 f1 = unpack2(b1p[1][c]);
        b1[0][c] = f0.x; b1[1][c] = f0.y; b1[2][c] = f1.x; b1[3][c] = f1.y;
    }

    float hnew[20];
#pragma unroll
    for (int j = 0; j < 8; j++) hnew[j] = s[j] + (CS2*b0s[j] + CV2*b0v[j]);
#pragma unroll
    for (int o = 0; o < 4; o++)
#pragma unroll
        for (int c = 0; c < 3; c++)
            hnew[8 + o*3 + c] = vf[o*3+c] + (CS2*bsv[o]*sh1[c] + CV2*b1[o][c]);

    {
        float4* op = (float4*)(out_he + (size_t)e*20);
        const float4* hp = (const float4*)hnew;
#pragma unroll
        for (int t = 0; t < 5; t++) op[t] = hp[t];
    }
    float nw = enorm[e];
    float* nf = &g_nodeftr[(size_t)dstI*20];
#pragma unroll
    for (int t = 0; t < 20; t++) atomicAdd(&nf[t], hnew[t]*nw);
}

__global__ __launch_bounds__(128) void node_kernel(
    const float* __restrict__ hn,
    const float* __restrict__ WgS, const float* __restrict__ WgV,
    const float* __restrict__ WoS, const float* __restrict__ WoV,
    float* __restrict__ out_hn, int N)
{
    const float RS8 = 0.35355339059327379f;  // 1/sqrt(8)
    int n = blockIdx.x*128 + threadIdx.x;
    if (n >= N) return;

    float cs[16], cv[8][3];
    const float* ph = hn + (size_t)n*20;
    const float* pf = g_nodeftr + (size_t)n*20;
#pragma unroll
    for (int j = 0; j < 8; j++) { cs[j] = ph[j]; cs[8+j] = pf[j]; }
#pragma unroll
    for (int i = 0; i < 4; i++)
#pragma unroll
        for (int c = 0; c < 3; c++) { cv[i][c] = ph[8+i*3+c]; cv[4+i][c] = pf[8+i*3+c]; }

    float gl[12];
#pragma unroll
    for (int o = 0; o < 12; o++) {
        float a = 0.f;
#pragma unroll
        for (int i = 0; i < 16; i++) a = fmaf(cs[i], __ldg(&WgS[i*12+o]), a);
        gl[o] = a * 0.25f;
    }
    float vl[4][3];
#pragma unroll
    for (int o = 0; o < 4; o++)
#pragma unroll
        for (int c = 0; c < 3; c++) {
            float a = 0.f;
#pragma unroll
            for (int i = 0; i < 8; i++) a = fmaf(cv[i][c], __ldg(&WgV[i*4+o]), a);
            vl[o][c] = a * RS8;
        }

    float ls[8], lg[4];
#pragma unroll
    for (int j = 0; j < 8; j++) ls[j] = fmaxf(gl[j], 0.f);
#pragma unroll
    for (int o = 0; o < 4; o++) lg[o] = fmaxf(gl[8+o], 0.f);

    float lv[4][3];
#pragma unroll
    for (int o = 0; o < 4; o++)
#pragma unroll
        for (int c = 0; c < 3; c++) lv[o][c] = vl[o][c] * lg[o];

    float os_[8];
#pragma unroll
    for (int o = 0; o < 8; o++) {
        float a = 0.f;
#pragma unroll
        for (int i = 0; i < 8; i++) a = fmaf(ls[i], __ldg(&WoS[i*8+o]), a);
        os_[o] = a * RS8;
    }
    float ov[4][3];
#pragma unroll
    for (int o = 0; o < 4; o++)
#pragma unroll
        for (int c = 0; c < 3; c++) {
            float a = 0.f;
#pragma unroll
            for (int i = 0; i < 4; i++) a = fmaf(lv[i][c], __ldg(&WoV[i*4+o]), a);
            ov[o][c] = a * 0.5f;
        }

    float* po = out_hn + (size_t)n*20;
#pragma unroll
    for (int j = 0; j < 8; j++) po[j] = ph[j] + os_[j];
#pragma unroll
    for (int o = 0; o < 4; o++)
#pragma unroll
        for (int c = 0; c < 3; c++) po[8+o*3+c] = ph[8+o*3+c] + ov[o][c];
}

extern "C" void kernel_launch(void* const* d_in, const int* in_sizes, int n_in,
                              void* d_out, int out_size) {
    const float* hn    = (const float*)d_in[0];
    const float* he    = (const float*)d_in[1];
    const int*   esrc  = (const int*)d_in[2];
    const int*   edst  = (const int*)d_in[3];
    const float* evec  = (const float*)d_in[4];
    const float* emb   = (const float*)d_in[5];
    const float* enorm = (const float*)d_in[6];
    const float* fcW1  = (const float*)d_in[8];
    const float* fcW2  = (const float*)d_in[9];
    const float* fc2W1 = (const float*)d_in[10];
    const float* fc2W2 = (const float*)d_in[11];
    const float* WgS   = (const float*)d_in[12];
    const float* WgV   = (const float*)d_in[13];
    const float* WoS   = (const float*)d_in[14];
    const float* WoV   = (const float*)d_in[15];

    int N = in_sizes[0] / 20;
    int E = in_sizes[1] / 20;

    float* out    = (float*)d_out;
    float* out_hn = out;                      // (N,20) first
    float* out_he = out + (size_t)N * 20;     // (E,20) second

    int n4 = (N * 20) / 4;
    zero_nf_kernel<<<(n4 + 255)/256, 256>>>(n4);
    edge_kernel<<<(E + 127)/128, 128>>>(hn, he, esrc, edst, evec, emb, enorm,
                                        fcW1, fcW2, fc2W1, fc2W2, out_he, E);
    node_kernel<<<(N + 127)/128, 128>>>(hn, WgS, WgV, WoS, WoV, out_hn, N);
}

// round 4
// speedup vs baseline: 2.0478x; 1.0633x over previous
#include <cuda_runtime.h>

#define NNODES_C 10000
#define NEDGES_C 160000
typedef unsigned long long u64;

__device__ float g_nodeftr[NNODES_C * 20];
__device__ float g_tmp[NEDGES_C * 20];

static __device__ __forceinline__ u64 pack2(float x) {
    u64 r;
    asm("mov.b64 %0, {%1, %1};" : "=l"(r) : "r"(__float_as_uint(x)));
    return r;
}
static __device__ __forceinline__ float2 unpack2(u64 v) {
    float lo, hi;
    asm("mov.b64 {%0, %1}, %2;" : "=f"(lo), "=f"(hi) : "l"(v));
    return make_float2(lo, hi);
}
static __device__ __forceinline__ u64 fma2(u64 a, u64 b, u64 c) {
    u64 d;
    asm("fma.rn.f32x2 %0, %1, %2, %3;" : "=l"(d) : "l"(a), "l"(b), "l"(c));
    return d;
}
static __device__ __forceinline__ void red4(float* p, float a, float b, float c, float d) {
    asm volatile("red.global.add.v4.f32 [%0], {%1, %2, %3, %4};"
                 :: "l"(p), "f"(a), "f"(b), "f"(c), "f"(d) : "memory");
}

__global__ void zero_nf_kernel(int n4) {
    int i = blockIdx.x * blockDim.x + threadIdx.x;
    if (i < n4) ((float4*)g_nodeftr)[i] = make_float4(0.f, 0.f, 0.f, 0.f);
}

// ============================ Kernel A: MLP1 + TP1 + gating ============================
__global__ __launch_bounds__(128, 3) void edge_tp1_kernel(
    const float* __restrict__ hn, const float* __restrict__ he,
    const int* __restrict__ esrc, const int* __restrict__ edst,
    const float* __restrict__ evec, const float* __restrict__ emb,
    const float* __restrict__ fcW1, const float* __restrict__ fcW2, int E)
{
    const float SQ3f    = 1.7320508075688772f;
    const float INVSQ3f = 0.57735026918962576f;
    const float RS10    = 0.31622776601683794f;
    const float CS1     = 0.14433756729740645f;   // 1/sqrt(48)
    const float CV1     = 0.20412414523193150f;   // 1/sqrt(24)

    __shared__ __align__(16) float sW1[160];
    __shared__ __align__(16) float sW2[9216];
    {
        const float4* g1 = (const float4*)fcW1;
        float4* d1 = (float4*)sW1;
        for (int t = threadIdx.x; t < 40; t += 128) {
            float4 a = g1[t]; d1[t] = make_float4(a.x*RS10, a.y*RS10, a.z*RS10, a.w*RS10);
        }
        const float4* g2 = (const float4*)fcW2;
        float4* d2 = (float4*)sW2;
        for (int t = threadIdx.x; t < 2304; t += 128) {
            float4 a = g2[t]; d2[t] = make_float4(a.x*0.25f, a.y*0.25f, a.z*0.25f, a.w*0.25f);
        }
    }
    __syncthreads();

    int e = blockIdx.x*128 + threadIdx.x;
    if (e >= E) return;

    // ---- gather ----
    int srcI = esrc[e], dstI = edst[e];
    float s[24], vf[36];
    {
        float4 r0[5], r1[5], r2[5];
        const float4* p = (const float4*)(he + (size_t)e*20);
#pragma unroll
        for (int i = 0; i < 5; i++) r0[i] = p[i];
        const float4* ps = (const float4*)(hn + (size_t)srcI*20);
#pragma unroll
        for (int i = 0; i < 5; i++) r1[i] = ps[i];
        const float4* pd = (const float4*)(hn + (size_t)dstI*20);
#pragma unroll
        for (int i = 0; i < 5; i++) r2[i] = pd[i];
        const float* re = (const float*)r0;
        const float* rs = (const float*)r1;
        const float* rd = (const float*)r2;
#pragma unroll
        for (int j = 0; j < 8; j++) { s[j] = re[j]; s[8+j] = rs[j]; s[16+j] = rd[j]; }
#pragma unroll
        for (int j = 0; j < 12; j++) { vf[j] = re[8+j]; vf[12+j] = rs[8+j]; vf[24+j] = rd[8+j]; }
    }

    float sh1[3];
    {
        float ex = evec[e*3+0], ey = evec[e*3+1], ez = evec[e*3+2];
        float nn = sqrtf(ex*ex + ey*ey + ez*ez) + 1e-12f;
        float f = SQ3f / nn;
        sh1[0] = ex*f; sh1[1] = ey*f; sh1[2] = ez*f;
    }

    // ---- h1 = relu(emb @ fcW1/sqrt(10)) ----
    u64 h1p[16];
    {
        float embr[10];
        const float2* pe2 = (const float2*)(emb + (size_t)e*10);
#pragma unroll
        for (int j = 0; j < 5; j++) { float2 t = pe2[j]; embr[2*j] = t.x; embr[2*j+1] = t.y; }
        const ulonglong2* W = (const ulonglong2*)sW1;
        u64 acc[8];
#pragma unroll
        for (int p = 0; p < 8; p++) acc[p] = 0ull;
#pragma unroll
        for (int j = 0; j < 10; j++) {
            u64 ej = pack2(embr[j]);
#pragma unroll
            for (int g = 0; g < 4; g++) {
                ulonglong2 w = W[j*4+g];
                acc[2*g]   = fma2(ej, w.x, acc[2*g]);
                acc[2*g+1] = fma2(ej, w.y, acc[2*g+1]);
            }
        }
#pragma unroll
        for (int p = 0; p < 8; p++) {
            float2 f = unpack2(acc[p]);
            h1p[2*p]   = pack2(fmaxf(f.x, 0.f));
            h1p[2*p+1] = pack2(fmaxf(f.y, 0.f));
        }
    }

    const ulonglong2* W2 = (const ulonglong2*)sW2;   // 144 chunks per k-row

    float dots[12];
#pragma unroll
    for (int i = 0; i < 12; i++)
        dots[i] = (vf[i*3+0]*sh1[0] + vf[i*3+1]*sh1[1] + vf[i*3+2]*sh1[2]) * INVSQ3f;

    // vs: chunk 72 + i*3 + g   (consumes dots)
    u64 a0vp[6];
#pragma unroll
    for (int p = 0; p < 6; p++) a0vp[p] = 0ull;
#pragma unroll 1
    for (int i = 0; i < 12; i++) {
        u64 di2 = pack2(dots[i]);
#pragma unroll
        for (int g = 0; g < 3; g++) {
            u64 aA = 0ull, aB = 0ull;
#pragma unroll
            for (int k = 0; k < 16; k++) {
                ulonglong2 w = W2[k*144 + 72 + i*3 + g];
                aA = fma2(h1p[k], w.x, aA);
                aB = fma2(h1p[k], w.y, aB);
            }
            a0vp[2*g]   = fma2(di2, aA, a0vp[2*g]);
            a0vp[2*g+1] = fma2(di2, aB, a0vp[2*g+1]);
        }
    }
    // vv: chunk 132 + i   (consumes vf)
    u64 a1p[2][3];
#pragma unroll
    for (int c = 0; c < 3; c++) { a1p[0][c] = 0ull; a1p[1][c] = 0ull; }
#pragma unroll 1
    for (int i = 0; i < 12; i++) {
        u64 aA = 0ull, aB = 0ull;
#pragma unroll
        for (int k = 0; k < 16; k++) {
            ulonglong2 w = W2[k*144 + 132 + i];
            aA = fma2(h1p[k], w.x, aA);
            aB = fma2(h1p[k], w.y, aB);
        }
#pragma unroll
        for (int c = 0; c < 3; c++) {
            u64 vc2 = pack2(vf[i*3+c]);
            a1p[0][c] = fma2(vc2, aA, a1p[0][c]);
            a1p[1][c] = fma2(vc2, aB, a1p[1][c]);
        }
    }
    // ss: chunk i*3 + g
    u64 a0sp[6];
#pragma unroll
    for (int p = 0; p < 6; p++) a0sp[p] = 0ull;
#pragma unroll 1
    for (int i = 0; i < 24; i++) {
        u64 si2 = pack2(s[i]);
#pragma unroll
        for (int g = 0; g < 3; g++) {
            u64 aA = 0ull, aB = 0ull;
#pragma unroll
            for (int k = 0; k < 16; k++) {
                ulonglong2 w = W2[k*144 + i*3 + g];
                aA = fma2(h1p[k], w.x, aA);
                aB = fma2(h1p[k], w.y, aB);
            }
            a0sp[2*g]   = fma2(si2, aA, a0sp[2*g]);
            a0sp[2*g+1] = fma2(si2, aB, a0sp[2*g+1]);
        }
    }
    // sv: chunk 108 + i   (consumes s)
    u64 asvp[2];
    asvp[0] = 0ull; asvp[1] = 0ull;
#pragma unroll 1
    for (int i = 0; i < 24; i++) {
        u64 aA = 0ull, aB = 0ull;
#pragma unroll
        for (int k = 0; k < 16; k++) {
            ulonglong2 w = W2[k*144 + 108 + i];
            aA = fma2(h1p[k], w.x, aA);
            aB = fma2(h1p[k], w.y, aB);
        }
        u64 si2 = pack2(s[i]);
        asvp[0] = fma2(si2, aA, asvp[0]);
        asvp[1] = fma2(si2, aB, asvp[1]);
    }

    // ---- gating -> tmp ----
    float outr[20];
    {
        float a0s[12], a0v[12], asv[4], a1[4][3];
#pragma unroll
        for (int p = 0; p < 6; p++) {
            float2 fs = unpack2(a0sp[p]); a0s[2*p] = fs.x; a0s[2*p+1] = fs.y;
            float2 fv = unpack2(a0vp[p]); a0v[2*p] = fv.x; a0v[2*p+1] = fv.y;
        }
        {
            float2 f0 = unpack2(asvp[0]); float2 f1 = unpack2(asvp[1]);
            asv[0] = f0.x; asv[1] = f0.y; asv[2] = f1.x; asv[3] = f1.y;
        }
#pragma unroll
        for (int c = 0; c < 3; c++) {
            float2 f0 = unpack2(a1p[0][c]); float2 f1 = unpack2(a1p[1][c]);
            a1[0][c] = f0.x; a1[1][c] = f0.y; a1[2][c] = f1.x; a1[3][c] = f1.y;
        }
#pragma unroll
        for (int o = 0; o < 8; o++) outr[o] = fmaxf(CS1*a0s[o] + CV1*a0v[o], 0.f);
#pragma unroll
        for (int o = 0; o < 4; o++) {
            float gate = fmaxf(CS1*a0s[8+o] + CV1*a0v[8+o], 0.f);
#pragma unroll
            for (int c = 0; c < 3; c++)
                outr[8 + o*3 + c] = (CS1*asv[o]*sh1[c] + CV1*a1[o][c]) * gate;
        }
    }
    {
        float4* tp = (float4*)(g_tmp + (size_t)e*20);
        const float4* sp = (const float4*)outr;
#pragma unroll
        for (int t = 0; t < 5; t++) tp[t] = sp[t];
    }
}

// ============================ Kernel B: MLP2 + TP2 + epilogue ============================
__global__ __launch_bounds__(128, 4) void edge_tp2_kernel(
    const float* __restrict__ he,
    const int* __restrict__ edst, const float* __restrict__ evec,
    const float* __restrict__ emb, const float* __restrict__ enorm,
    const float* __restrict__ fc2W1, const float* __restrict__ fc2W2,
    float* __restrict__ out_he, int E)
{
    const float SQ3f    = 1.7320508075688772f;
    const float INVSQ3f = 0.57735026918962576f;
    const float RS10    = 0.31622776601683794f;
    const float CS2     = 0.25f;
    const float CV2     = 0.35355339059327379f;

    __shared__ __align__(16) float sW1b[160];
    __shared__ __align__(16) float sW2b[2304];
    {
        const float4* g1b = (const float4*)fc2W1;
        float4* d1b = (float4*)sW1b;
        for (int t = threadIdx.x; t < 40; t += 128) {
            float4 b = g1b[t]; d1b[t] = make_float4(b.x*RS10, b.y*RS10, b.z*RS10, b.w*RS10);
        }
        const float4* g2b = (const float4*)fc2W2;
        float4* d2b = (float4*)sW2b;
        for (int t = threadIdx.x; t < 576; t += 128) {
            float4 a = g2b[t]; d2b[t] = make_float4(a.x*0.25f, a.y*0.25f, a.z*0.25f, a.w*0.25f);
        }
    }
    __syncthreads();

    int e = blockIdx.x*128 + threadIdx.x;
    if (e >= E) return;

    // load gated intermediates
    float ts[8], tv[12];
    {
        float4 r[5];
        const float4* tp = (const float4*)(g_tmp + (size_t)e*20);
#pragma unroll
        for (int i = 0; i < 5; i++) r[i] = tp[i];
        const float* f = (const float*)r;
#pragma unroll
        for (int j = 0; j < 8; j++) ts[j] = f[j];
#pragma unroll
        for (int j = 0; j < 12; j++) tv[j] = f[8+j];
    }

    float sh1[3];
    {
        float ex = evec[e*3+0], ey = evec[e*3+1], ez = evec[e*3+2];
        float nn = sqrtf(ex*ex + ey*ey + ez*ez) + 1e-12f;
        float f = SQ3f / nn;
        sh1[0] = ex*f; sh1[1] = ey*f; sh1[2] = ez*f;
    }
    float dt[4];
#pragma unroll
    for (int i = 0; i < 4; i++)
        dt[i] = (tv[i*3+0]*sh1[0] + tv[i*3+1]*sh1[1] + tv[i*3+2]*sh1[2]) * INVSQ3f;

    // ---- h2 ----
    u64 h2p[16];
    {
        float embr[10];
        const float2* pe2 = (const float2*)(emb + (size_t)e*10);
#pragma unroll
        for (int j = 0; j < 5; j++) { float2 t = pe2[j]; embr[2*j] = t.x; embr[2*j+1] = t.y; }
        const ulonglong2* W = (const ulonglong2*)sW1b;
        u64 acc[8];
#pragma unroll
        for (int p = 0; p < 8; p++) acc[p] = 0ull;
#pragma unroll
        for (int j = 0; j < 10; j++) {
            u64 ej = pack2(embr[j]);
#pragma unroll
            for (int g = 0; g < 4; g++) {
                ulonglong2 w = W[j*4+g];
                acc[2*g]   = fma2(ej, w.x, acc[2*g]);
                acc[2*g+1] = fma2(ej, w.y, acc[2*g+1]);
            }
        }
#pragma unroll
        for (int p = 0; p < 8; p++) {
            float2 f = unpack2(acc[p]);
            h2p[2*p]   = pack2(fmaxf(f.x, 0.f));
            h2p[2*p+1] = pack2(fmaxf(f.y, 0.f));
        }
    }

    // ---- TP2 ----
    const ulonglong2* W2b = (const ulonglong2*)sW2b;  // 36 chunks per k-row
    u64 b0sp[4], b0vp[4], bsvp[2], b1p[2][3];
#pragma unroll
    for (int p = 0; p < 4; p++) { b0sp[p] = 0ull; b0vp[p] = 0ull; }
    bsvp[0] = 0ull; bsvp[1] = 0ull;
#pragma unroll
    for (int c = 0; c < 3; c++) { b1p[0][c] = 0ull; b1p[1][c] = 0ull; }

    // ss: chunk i*2 + g
#pragma unroll 1
    for (int i = 0; i < 8; i++) {
        u64 si2 = pack2(ts[i]);
#pragma unroll
        for (int g = 0; g < 2; g++) {
            u64 aA = 0ull, aB = 0ull;
#pragma unroll
            for (int k = 0; k < 16; k++) {
                ulonglong2 w = W2b[k*36 + i*2 + g];
                aA = fma2(h2p[k], w.x, aA);
                aB = fma2(h2p[k], w.y, aB);
            }
            b0sp[2*g]   = fma2(si2, aA, b0sp[2*g]);
            b0sp[2*g+1] = fma2(si2, aB, b0sp[2*g+1]);
        }
    }
    // vs: chunk 16 + i*2 + g
#pragma unroll 1
    for (int i = 0; i < 4; i++) {
        u64 di2 = pack2(dt[i]);
#pragma unroll
        for (int g = 0; g < 2; g++) {
            u64 aA = 0ull, aB = 0ull;
#pragma unroll
            for (int k = 0; k < 16; k++) {
                ulonglong2 w = W2b[k*36 + 16 + i*2 + g];
                aA = fma2(h2p[k], w.x, aA);
                aB = fma2(h2p[k], w.y, aB);
            }
            b0vp[2*g]   = fma2(di2, aA, b0vp[2*g]);
            b0vp[2*g+1] = fma2(di2, aB, b0vp[2*g+1]);
        }
    }
    // sv: chunk 24 + i
#pragma unroll 1
    for (int i = 0; i < 8; i++) {
        u64 aA = 0ull, aB = 0ull;
#pragma unroll
        for (int k = 0; k < 16; k++) {
            ulonglong2 w = W2b[k*36 + 24 + i];
            aA = fma2(h2p[k], w.x, aA);
            aB = fma2(h2p[k], w.y, aB);
        }
        u64 si2 = pack2(ts[i]);
        bsvp[0] = fma2(si2, aA, bsvp[0]);
        bsvp[1] = fma2(si2, aB, bsvp[1]);
    }
    // vv: chunk 32 + i
#pragma unroll 1
    for (int i = 0; i < 4; i++) {
        u64 aA = 0ull, aB = 0ull;
#pragma unroll
        for (int k = 0; k < 16; k++) {
            ulonglong2 w = W2b[k*36 + 32 + i];
            aA = fma2(h2p[k], w.x, aA);
            aB = fma2(h2p[k], w.y, aB);
        }
#pragma unroll
        for (int c = 0; c < 3; c++) {
            u64 vc2 = pack2(tv[i*3+c]);
            b1p[0][c] = fma2(vc2, aA, b1p[0][c]);
            b1p[1][c] = fma2(vc2, aB, b1p[1][c]);
        }
    }

    // ---- epilogue ----
    float b0s[8], b0v[8], bsv[4], b1[4][3];
#pragma unroll
    for (int p = 0; p < 4; p++) {
        float2 fs = unpack2(b0sp[p]); b0s[2*p] = fs.x; b0s[2*p+1] = fs.y;
        float2 fv = unpack2(b0vp[p]); b0v[2*p] = fv.x; b0v[2*p+1] = fv.y;
    }
    {
        float2 f0 = unpack2(bsvp[0]); float2 f1 = unpack2(bsvp[1]);
        bsv[0] = f0.x; bsv[1] = f0.y; bsv[2] = f1.x; bsv[3] = f1.y;
    }
#pragma unroll
    for (int c = 0; c < 3; c++) {
        float2 f0 = unpack2(b1p[0][c]); float2 f1 = unpack2(b1p[1][c]);
        b1[0][c] = f0.x; b1[1][c] = f0.y; b1[2][c] = f1.x; b1[3][c] = f1.y;
    }

    float hnew[20];
    {
        float4 r[5];
        const float4* p = (const float4*)(he + (size_t)e*20);
#pragma unroll
        for (int i = 0; i < 5; i++) r[i] = p[i];
        const float* re = (const float*)r;
#pragma unroll
        for (int j = 0; j < 8; j++) hnew[j] = re[j] + (CS2*b0s[j] + CV2*b0v[j]);
#pragma unroll
        for (int o = 0; o < 4; o++)
#pragma unroll
            for (int c = 0; c < 3; c++)
                hnew[8 + o*3 + c] = re[8+o*3+c] + (CS2*bsv[o]*sh1[c] + CV2*b1[o][c]);
    }

    {
        float4* op = (float4*)(out_he + (size_t)e*20);
        const float4* hp = (const float4*)hnew;
#pragma unroll
        for (int t = 0; t < 5; t++) op[t] = hp[t];
    }
    int dstI = edst[e];
    float nw = enorm[e];
    float* nf = &g_nodeftr[(size_t)dstI*20];
#pragma unroll
    for (int t = 0; t < 5; t++)
        red4(nf + t*4, hnew[t*4]*nw, hnew[t*4+1]*nw, hnew[t*4+2]*nw, hnew[t*4+3]*nw);
}

// ============================ node kernel ============================
__global__ __launch_bounds__(128) void node_kernel(
    const float* __restrict__ hn,
    const float* __restrict__ WgS, const float* __restrict__ WgV,
    const float* __restrict__ WoS, const float* __restrict__ WoV,
    float* __restrict__ out_hn, int N)
{
    const float RS8 = 0.35355339059327379f;
    int n = blockIdx.x*128 + threadIdx.x;
    if (n >= N) return;

    float cs[16], cv[8][3];
    const float* ph = hn + (size_t)n*20;
    const float* pf = g_nodeftr + (size_t)n*20;
#pragma unroll
    for (int j = 0; j < 8; j++) { cs[j] = ph[j]; cs[8+j] = pf[j]; }
#pragma unroll
    for (int i = 0; i < 4; i++)
#pragma unroll
        for (int c = 0; c < 3; c++) { cv[i][c] = ph[8+i*3+c]; cv[4+i][c] = pf[8+i*3+c]; }

    float gl[12];
#pragma unroll
    for (int o = 0; o < 12; o++) {
        float a = 0.f;
#pragma unroll
        for (int i = 0; i < 16; i++) a = fmaf(cs[i], __ldg(&WgS[i*12+o]), a);
        gl[o] = a * 0.25f;
    }
    float vl[4][3];
#pragma unroll
    for (int o = 0; o < 4; o++)
#pragma unroll
        for (int c = 0; c < 3; c++) {
            float a = 0.f;
#pragma unroll
            for (int i = 0; i < 8; i++) a = fmaf(cv[i][c], __ldg(&WgV[i*4+o]), a);
            vl[o][c] = a * RS8;
        }

    float ls[8], lg[4];
#pragma unroll
    for (int j = 0; j < 8; j++) ls[j] = fmaxf(gl[j], 0.f);
#pragma unroll
    for (int o = 0; o < 4; o++) lg[o] = fmaxf(gl[8+o], 0.f);

    float lv[4][3];
#pragma unroll
    for (int o = 0; o < 4; o++)
#pragma unroll
        for (int c = 0; c < 3; c++) lv[o][c] = vl[o][c] * lg[o];

    float os_[8];
#pragma unroll
    for (int o = 0; o < 8; o++) {
        float a = 0.f;
#pragma unroll
        for (int i = 0; i < 8; i++) a = fmaf(ls[i], __ldg(&WoS[i*8+o]), a);
        os_[o] = a * RS8;
    }
    float ov[4][3];
#pragma unroll
    for (int o = 0; o < 4; o++)
#pragma unroll
        for (int c = 0; c < 3; c++) {
            float a = 0.f;
#pragma unroll
            for (int i = 0; i < 4; i++) a = fmaf(lv[i][c], __ldg(&WoV[i*4+o]), a);
            ov[o][c] = a * 0.5f;
        }

    float* po = out_hn + (size_t)n*20;
#pragma unroll
    for (int j = 0; j < 8; j++) po[j] = ph[j] + os_[j];
#pragma unroll
    for (int o = 0; o < 4; o++)
#pragma unroll
        for (int c = 0; c < 3; c++) po[8+o*3+c] = ph[8+o*3+c] + ov[o][c];
}

extern "C" void kernel_launch(void* const* d_in, const int* in_sizes, int n_in,
                              void* d_out, int out_size) {
    const float* hn    = (const float*)d_in[0];
    const float* he    = (const float*)d_in[1];
    const int*   esrc  = (const int*)d_in[2];
    const int*   edst  = (const int*)d_in[3];
    const float* evec  = (const float*)d_in[4];
    const float* emb   = (const float*)d_in[5];
    const float* enorm = (const float*)d_in[6];
    const float* fcW1  = (const float*)d_in[8];
    const float* fcW2  = (const float*)d_in[9];
    const float* fc2W1 = (const float*)d_in[10];
    const float* fc2W2 = (const float*)d_in[11];
    const float* WgS   = (const float*)d_in[12];
    const float* WgV   = (const float*)d_in[13];
    const float* WoS   = (const float*)d_in[14];
    const float* WoV   = (const float*)d_in[15];

    int N = in_sizes[0] / 20;
    int E = in_sizes[1] / 20;

    float* out    = (float*)d_out;
    float* out_hn = out;                      // (N,20) first
    float* out_he = out + (size_t)N * 20;     // (E,20) second

    int n4 = (N * 20) / 4;
    zero_nf_kernel<<<(n4 + 255)/256, 256>>>(n4);
    edge_tp1_kernel<<<(E + 127)/128, 128>>>(hn, he, esrc, edst, evec, emb, fcW1, fcW2, E);
    edge_tp2_kernel<<<(E + 127)/128, 128>>>(he, edst, evec, emb, enorm, fc2W1, fc2W2, out_he, E);
    node_kernel<<<(N + 127)/128, 128>>>(hn, WgS, WgV, WoS, WoV, out_hn, N);
}